// round 8
// baseline (speedup 1.0000x reference)
#include <cuda_runtime.h>
#include <cuda_bf16.h>
#include <cstdint>

// ---------------- problem constants ----------------
#define BATCH    1024
#define NITEMS   100000
#define EMB      128
#define TOPK     50

// gemm1 tiling
#define SPLIT    50          // K-split over NITEMS
#define KC       2000        // NITEMS / SPLIT
#define TI       16          // i-chunk staged in smem (KC % TI == 0)
#define RB1      64          // rows per block

// gemm2 tiling
#define JT       128         // items per block
#define RT       64          // rows per block
#define G2_THREADS 256

#define CAND_TARGET 256      // candidate pool target (margin over TOPK)
#define CAND_MAX    2048

// ---------------- device scratch (static: no allocations) ----------------
__device__ float g_part[(size_t)SPLIT * BATCH * EMB];   // 25.6 MB
__device__ float g_xemb[BATCH * EMB];                   // 0.5 MB
__device__ float g_ET[(size_t)EMB * NITEMS];            // 51.2 MB (E^T, [d][j])
__device__ float g_scores[(size_t)BATCH * NITEMS];      // 409.6 MB

// ---------------- kernel 1: x_emb partials = x @ E (K-split) ----------------
// fp32 FMA inner loop; every TI=16 items the fp32 sub-sums fold into fp64
// accumulators (error ~7e-7 per chunk, fold exact).
__global__ __launch_bounds__(256) void k_gemm1(const float* __restrict__ x,
                                               const float* __restrict__ E) {
    __shared__ float xs[TI][RB1 + 8];
    const int tid  = threadIdx.x;
    const int dg   = tid & 31;
    const int rg   = tid >> 5;
    const int row0 = blockIdx.x * RB1;
    const int s    = blockIdx.y;
    const int i0   = s * KC;
    const int d0   = dg * 4;
    const int r0   = rg * 8;

    double acc64[8][4];
    #pragma unroll
    for (int r = 0; r < 8; r++)
        #pragma unroll
        for (int c = 0; c < 4; c++) acc64[r][c] = 0.0;

    for (int ic = 0; ic < KC; ic += TI) {
        __syncthreads();
        for (int t = tid; t < RB1 * (TI / 4); t += 256) {
            int r  = t >> 2;
            int iv = t & 3;
            float4 v = *reinterpret_cast<const float4*>(
                &x[(size_t)(row0 + r) * NITEMS + i0 + ic + iv * 4]);
            xs[iv * 4 + 0][r] = v.x;
            xs[iv * 4 + 1][r] = v.y;
            xs[iv * 4 + 2][r] = v.z;
            xs[iv * 4 + 3][r] = v.w;
        }
        __syncthreads();

        float facc[8][4];
        #pragma unroll
        for (int r = 0; r < 8; r++)
            #pragma unroll
            for (int c = 0; c < 4; c++) facc[r][c] = 0.f;

        #pragma unroll 4
        for (int k = 0; k < TI; k++) {
            float4 ev = *reinterpret_cast<const float4*>(
                &E[(size_t)(i0 + ic + k) * EMB + d0]);
            float4 xa = *reinterpret_cast<const float4*>(&xs[k][r0]);
            float4 xb = *reinterpret_cast<const float4*>(&xs[k][r0 + 4]);
            float xr[8] = {xa.x, xa.y, xa.z, xa.w, xb.x, xb.y, xb.z, xb.w};
            float ec[4] = {ev.x, ev.y, ev.z, ev.w};
            #pragma unroll
            for (int r = 0; r < 8; r++)
                #pragma unroll
                for (int c = 0; c < 4; c++)
                    facc[r][c] = fmaf(xr[r], ec[c], facc[r][c]);
        }
        #pragma unroll
        for (int r = 0; r < 8; r++)
            #pragma unroll
            for (int c = 0; c < 4; c++) acc64[r][c] += (double)facc[r][c];
    }

    float* part = &g_part[(size_t)s * BATCH * EMB];
    #pragma unroll
    for (int r = 0; r < 8; r++) {
        *reinterpret_cast<float4*>(&part[(size_t)(row0 + r0 + r) * EMB + d0]) =
            make_float4((float)acc64[r][0], (float)acc64[r][1],
                        (float)acc64[r][2], (float)acc64[r][3]);
    }
}

// ---------------- kernel 1b: fold K-split partials in fp64 ----------------
__global__ __launch_bounds__(256) void k_reduce() {
    int i = blockIdx.x * blockDim.x + threadIdx.x;
    if (i < BATCH * EMB) {
        double sum = 0.0;
        #pragma unroll
        for (int s = 0; s < SPLIT; s++) sum += (double)g_part[(size_t)s * BATCH * EMB + i];
        g_xemb[i] = (float)sum;
    }
}

// ---------------- kernel: transpose E -> g_ET[d][j] ----------------
__global__ void k_transposeE(const float* __restrict__ E) {
    __shared__ float tile[32][33];
    int j0 = blockIdx.x * 32;
    int d0 = blockIdx.y * 32;
    for (int jj = threadIdx.y; jj < 32; jj += 8)
        tile[jj][threadIdx.x] = E[(size_t)(j0 + jj) * EMB + d0 + threadIdx.x];
    __syncthreads();
    for (int dd = threadIdx.y; dd < 32; dd += 8)
        g_ET[(size_t)(d0 + dd) * NITEMS + j0 + threadIdx.x] = tile[threadIdx.x][dd];
}

// ---------------- kernel 2: scores = x_emb @ E^T (fp32; ranking-grade only) ----
__global__ __launch_bounds__(G2_THREADS) void k_gemm2() {
    __shared__ float xe[EMB][RT + 4];
    const int tid  = threadIdx.x;
    const int jg   = tid & 31;
    const int rg   = tid >> 5;
    const int row0 = blockIdx.y * RT;
    const int jb   = blockIdx.x * JT;
    const int r0   = rg * 8;

    for (int t = tid; t < RT * EMB; t += G2_THREADS) {
        int r = t >> 7, d = t & 127;
        xe[d][r] = g_xemb[(size_t)(row0 + r) * EMB + d];
    }
    __syncthreads();

    int jz = jb + jg * 4;
    int j0 = (jz <= NITEMS - 4) ? jz : (NITEMS - 4);

    float acc[8][4];
    #pragma unroll
    for (int r = 0; r < 8; r++)
        #pragma unroll
        for (int c = 0; c < 4; c++) acc[r][c] = 0.f;

    #pragma unroll 4
    for (int dd = 0; dd < EMB; dd++) {
        float4 ev = *reinterpret_cast<const float4*>(&g_ET[(size_t)dd * NITEMS + j0]);
        float4 xa = *reinterpret_cast<const float4*>(&xe[dd][r0]);
        float4 xb = *reinterpret_cast<const float4*>(&xe[dd][r0 + 4]);
        float xr[8] = {xa.x, xa.y, xa.z, xa.w, xb.x, xb.y, xb.z, xb.w};
        float ec[4] = {ev.x, ev.y, ev.z, ev.w};
        #pragma unroll
        for (int r = 0; r < 8; r++)
            #pragma unroll
            for (int c = 0; c < 4; c++)
                acc[r][c] = fmaf(xr[r], ec[c], acc[r][c]);
    }

    if (jz <= NITEMS - 4) {
        #pragma unroll
        for (int r = 0; r < 8; r++) {
            *reinterpret_cast<float4*>(&g_scores[(size_t)(row0 + r0 + r) * NITEMS + jz]) =
                make_float4(acc[r][0], acc[r][1], acc[r][2], acc[r][3]);
        }
    }
}

// ---------------- kernel 3: candidate top-256 by fp32, fp64 rescore, top-50 ----
__device__ __forceinline__ unsigned ordu(float f) {
    unsigned u = __float_as_uint(f);
    return (u & 0x80000000u) ? ~u : (u | 0x80000000u);
}
__device__ __forceinline__ unsigned long long ordu64(double d) {
    unsigned long long u = __double_as_longlong(d);
    return (u & 0x8000000000000000ull) ? ~u : (u | 0x8000000000000000ull);
}

__global__ __launch_bounds__(256) void k_topk(const float* __restrict__ E,
                                              float* __restrict__ out) {
    __shared__ union {
        unsigned hist[4096];                    // pass 1/2
        unsigned long long keys[CAND_MAX];      // rescore/select (aliased after scan)
    } u;
    __shared__ unsigned cidx[CAND_MAX];
    __shared__ float xrow[EMB];
    __shared__ unsigned strip[256];
    __shared__ int s_bin, s_cnt;
    __shared__ unsigned long long wkey[8];
    __shared__ unsigned wbi[8];
    __shared__ int wpos[8];

    const int row = blockIdx.x;
    const int tid = threadIdx.x;
    const int lane = tid & 31;
    const int warp = tid >> 5;
    const float4* s4 = reinterpret_cast<const float4*>(&g_scores[(size_t)row * NITEMS]);

    if (tid < EMB) xrow[tid] = g_xemb[row * EMB + tid];
    for (int b = tid; b < 4096; b += 256) u.hist[b] = 0;
    __syncthreads();

    // pass 1: 12-bit histogram of ordered-uint
    for (int i = tid; i < NITEMS / 4; i += 256) {
        float4 v = s4[i];
        atomicAdd(&u.hist[ordu(v.x) >> 20], 1u);
        atomicAdd(&u.hist[ordu(v.y) >> 20], 1u);
        atomicAdd(&u.hist[ordu(v.z) >> 20], 1u);
        atomicAdd(&u.hist[ordu(v.w) >> 20], 1u);
    }
    __syncthreads();

    // suffix scan for bin with above-count < CAND_TARGET <= inclusive-count
    unsigned loc = 0;
    #pragma unroll
    for (int q = 0; q < 16; q++) loc += u.hist[tid * 16 + q];
    strip[tid] = loc;
    __syncthreads();
    if (tid == 0) {
        int acc = 0, bin = 0;
        for (int t = 255; t >= 0; t--) {
            if (acc + (int)strip[t] >= CAND_TARGET) {
                for (int b = t * 16 + 15; b >= t * 16; b--) {
                    if (acc + (int)u.hist[b] >= CAND_TARGET) { bin = b; break; }
                    acc += (int)u.hist[b];
                }
                break;
            }
            acc += (int)strip[t];
        }
        s_bin = bin; s_cnt = 0;
    }
    __syncthreads();

    // pass 2: compact candidate indices (u >= bin lower edge)
    const unsigned thresh = ((unsigned)s_bin) << 20;
    for (int i = tid; i < NITEMS / 4; i += 256) {
        float4 v = s4[i];
        float vv[4] = {v.x, v.y, v.z, v.w};
        #pragma unroll
        for (int c = 0; c < 4; c++) {
            if (ordu(vv[c]) >= thresh) {
                int p = atomicAdd(&s_cnt, 1);
                if (p < CAND_MAX) cidx[p] = (unsigned)(4 * i + c);
            }
        }
    }
    __syncthreads();
    int cnt = s_cnt < CAND_MAX ? s_cnt : CAND_MAX;

    // fail-safe (unreachable on healthy data)
    if (cnt < TOPK) {
        for (int i = tid; i < CAND_MAX; i += 256) cidx[i] = (unsigned)i;
        cnt = CAND_MAX;
        __syncthreads();
    }

    // fp64 rescore: one warp per candidate; lane owns 4 dims (float4 load of E row)
    __syncthreads();   // hist reads done; safe to alias u.keys
    for (int c = warp; c < cnt; c += 8) {
        const unsigned j = cidx[c];
        const float4* Ej4 = reinterpret_cast<const float4*>(&E[(size_t)j * EMB]);
        float4 ev = __ldg(&Ej4[lane]);
        const float4* xv4 = reinterpret_cast<const float4*>(&xrow[lane * 4]);
        float4 xv = *xv4;
        double s = (double)xv.x * (double)ev.x + (double)xv.y * (double)ev.y
                 + (double)xv.z * (double)ev.z + (double)xv.w * (double)ev.w;
        #pragma unroll
        for (int off = 16; off; off >>= 1)
            s += __shfl_down_sync(0xffffffffu, s, off);
        if (lane == 0) u.keys[c] = ordu64(s);
    }
    __syncthreads();

    // 50 selections: fp64 value desc, item index asc on ties
    for (int k = 0; k < TOPK; k++) {
        unsigned long long bk = 0; unsigned bi = 0xffffffffu; int bp = -1;
        for (int i = tid; i < cnt; i += 256) {
            unsigned long long kk = u.keys[i];
            unsigned ii = cidx[i];
            if (kk > bk || (kk == bk && ii < bi)) { bk = kk; bi = ii; bp = i; }
        }
        #pragma unroll
        for (int off = 16; off; off >>= 1) {
            unsigned long long ok = __shfl_down_sync(0xffffffffu, bk, off);
            unsigned oi = __shfl_down_sync(0xffffffffu, bi, off);
            int op = __shfl_down_sync(0xffffffffu, bp, off);
            if (ok > bk || (ok == bk && oi < bi)) { bk = ok; bi = oi; bp = op; }
        }
        if (lane == 0) { wkey[warp] = bk; wbi[warp] = bi; wpos[warp] = bp; }
        __syncthreads();
        if (tid == 0) {
            unsigned long long fb = 0; unsigned fi = 0xffffffffu; int fp = -1;
            #pragma unroll
            for (int w = 0; w < 8; w++)
                if (wkey[w] > fb || (wkey[w] == fb && wbi[w] < fi)) {
                    fb = wkey[w]; fi = wbi[w]; fp = wpos[w];
                }
            out[row * TOPK + k] = (float)fi;     // float32 index output
            if (fp >= 0) u.keys[fp] = 0;         // remove winner (real keys > 0)
        }
        __syncthreads();
    }
}

// ---------------- launch ----------------
extern "C" void kernel_launch(void* const* d_in, const int* in_sizes, int n_in,
                              void* d_out, int out_size) {
    const float* a0 = (const float*)d_in[0];
    const float* a1 = (const float*)d_in[1];
    const bool first_is_x = (in_sizes[0] == BATCH * NITEMS) ||
                            (in_sizes[0] == BATCH * NITEMS * 4);
    const float* x = first_is_x ? a0 : a1;             // [1024, 100000]
    const float* E = first_is_x ? a1 : a0;             // [100000, 128]
    float* out = (float*)d_out;                        // [1024, 50] float32 indices

    k_transposeE<<<dim3(NITEMS / 32, EMB / 32), dim3(32, 8)>>>(E);
    k_gemm1<<<dim3(BATCH / RB1, SPLIT), 256>>>(x, E);
    k_reduce<<<(BATCH * EMB + 255) / 256, 256>>>();
    k_gemm2<<<dim3((NITEMS + JT - 1) / JT, BATCH / RT), G2_THREADS>>>();
    k_topk<<<BATCH, 256>>>(E, out);
}

// round 9
// speedup vs baseline: 1.8422x; 1.8422x over previous
#include <cuda_runtime.h>
#include <cuda_bf16.h>
#include <cstdint>

// ---------------- problem constants ----------------
#define BATCH    1024
#define NITEMS   100000
#define EMB      128
#define TOPK     50

// gemm1 tiling
#define SPLIT    50          // K-split over NITEMS
#define KC       2000        // NITEMS / SPLIT
#define TI       16          // i-chunk staged in smem (KC % TI == 0)
#define RB1      64          // rows per block

// gemm2 tiling
#define JT       256         // items per block (8 per thread)
#define RT       64          // rows per block  (8 per thread)
#define G2_THREADS 256

#define CAND_TARGET 256      // candidate pool target (margin over TOPK)
#define CAND_MAX    2048

// ---------------- device scratch (static: no allocations) ----------------
__device__ float g_part[(size_t)SPLIT * BATCH * EMB];   // 25.6 MB
__device__ float g_xemb[BATCH * EMB];                   // 0.5 MB
__device__ float g_ET[(size_t)EMB * NITEMS];            // 51.2 MB (E^T, [d][j])
__device__ float g_scores[(size_t)BATCH * NITEMS];      // 409.6 MB

// ---------------- kernel 1: x_emb partials = x @ E (K-split) ----------------
// All-fp32 two-level accumulation: facc per 16-item chunk (|chunk|~4),
// folded into fp32 gacc (|gacc|~45). Chunk-internal noise dominates either way;
// removes the fp64 pipe tax (~8x FMA time) of the previous version.
__global__ __launch_bounds__(256) void k_gemm1(const float* __restrict__ x,
                                               const float* __restrict__ E) {
    __shared__ float xs[TI][RB1 + 8];
    const int tid  = threadIdx.x;
    const int dg   = tid & 31;
    const int rg   = tid >> 5;
    const int row0 = blockIdx.x * RB1;
    const int s    = blockIdx.y;
    const int i0   = s * KC;
    const int d0   = dg * 4;
    const int r0   = rg * 8;

    float gacc[8][4];
    #pragma unroll
    for (int r = 0; r < 8; r++)
        #pragma unroll
        for (int c = 0; c < 4; c++) gacc[r][c] = 0.f;

    for (int ic = 0; ic < KC; ic += TI) {
        __syncthreads();
        for (int t = tid; t < RB1 * (TI / 4); t += 256) {
            int r  = t >> 2;
            int iv = t & 3;
            float4 v = *reinterpret_cast<const float4*>(
                &x[(size_t)(row0 + r) * NITEMS + i0 + ic + iv * 4]);
            xs[iv * 4 + 0][r] = v.x;
            xs[iv * 4 + 1][r] = v.y;
            xs[iv * 4 + 2][r] = v.z;
            xs[iv * 4 + 3][r] = v.w;
        }
        __syncthreads();

        float facc[8][4];
        #pragma unroll
        for (int r = 0; r < 8; r++)
            #pragma unroll
            for (int c = 0; c < 4; c++) facc[r][c] = 0.f;

        #pragma unroll
        for (int k = 0; k < TI; k++) {
            float4 ev = *reinterpret_cast<const float4*>(
                &E[(size_t)(i0 + ic + k) * EMB + d0]);
            float4 xa = *reinterpret_cast<const float4*>(&xs[k][r0]);
            float4 xb = *reinterpret_cast<const float4*>(&xs[k][r0 + 4]);
            float xr[8] = {xa.x, xa.y, xa.z, xa.w, xb.x, xb.y, xb.z, xb.w};
            float ec[4] = {ev.x, ev.y, ev.z, ev.w};
            #pragma unroll
            for (int r = 0; r < 8; r++)
                #pragma unroll
                for (int c = 0; c < 4; c++)
                    facc[r][c] = fmaf(xr[r], ec[c], facc[r][c]);
        }
        #pragma unroll
        for (int r = 0; r < 8; r++)
            #pragma unroll
            for (int c = 0; c < 4; c++) gacc[r][c] += facc[r][c];
    }

    float* part = &g_part[(size_t)s * BATCH * EMB];
    #pragma unroll
    for (int r = 0; r < 8; r++) {
        *reinterpret_cast<float4*>(&part[(size_t)(row0 + r0 + r) * EMB + d0]) =
            make_float4(gacc[r][0], gacc[r][1], gacc[r][2], gacc[r][3]);
    }
}

// ---------------- kernel 1b: fold K-split partials in fp64 (tiny kernel) -------
__global__ __launch_bounds__(256) void k_reduce() {
    int i = blockIdx.x * blockDim.x + threadIdx.x;
    if (i < BATCH * EMB) {
        double sum = 0.0;
        #pragma unroll
        for (int s = 0; s < SPLIT; s++) sum += (double)g_part[(size_t)s * BATCH * EMB + i];
        g_xemb[i] = (float)sum;
    }
}

// ---------------- kernel: transpose E -> g_ET[d][j] ----------------
__global__ void k_transposeE(const float* __restrict__ E) {
    __shared__ float tile[32][33];
    int j0 = blockIdx.x * 32;
    int d0 = blockIdx.y * 32;
    for (int jj = threadIdx.y; jj < 32; jj += 8)
        tile[jj][threadIdx.x] = E[(size_t)(j0 + jj) * EMB + d0 + threadIdx.x];
    __syncthreads();
    for (int dd = threadIdx.y; dd < 32; dd += 8)
        g_ET[(size_t)(d0 + dd) * NITEMS + j0 + threadIdx.x] = tile[threadIdx.x][dd];
}

// ---------------- kernel 2: scores = x_emb @ E^T (fp32; ranking-grade) ----------
// 8 rows x 8 items per thread: halves LDS+LDG issue per FMA vs 8x4.
__global__ __launch_bounds__(G2_THREADS) void k_gemm2() {
    __shared__ float xe[EMB][RT + 4];
    const int tid  = threadIdx.x;
    const int jg   = tid & 31;        // item group (8 items)
    const int rg   = tid >> 5;        // row group (8 rows)
    const int row0 = blockIdx.y * RT;
    const int jb   = blockIdx.x * JT;
    const int r0   = rg * 8;

    for (int t = tid; t < RT * EMB; t += G2_THREADS) {
        int r = t >> 7, d = t & 127;
        xe[d][r] = g_xemb[(size_t)(row0 + r) * EMB + d];
    }
    __syncthreads();

    int jz = jb + jg * 8;
    int j0 = (jz <= NITEMS - 8) ? jz : (NITEMS - 8);   // clamp for loads only

    float acc[8][8];
    #pragma unroll
    for (int r = 0; r < 8; r++)
        #pragma unroll
        for (int c = 0; c < 8; c++) acc[r][c] = 0.f;

    #pragma unroll 2
    for (int dd = 0; dd < EMB; dd++) {
        const float* etp = &g_ET[(size_t)dd * NITEMS + j0];
        float4 e0 = *reinterpret_cast<const float4*>(etp);
        float4 e1 = *reinterpret_cast<const float4*>(etp + 4);
        float4 xa = *reinterpret_cast<const float4*>(&xe[dd][r0]);
        float4 xb = *reinterpret_cast<const float4*>(&xe[dd][r0 + 4]);
        float xr[8] = {xa.x, xa.y, xa.z, xa.w, xb.x, xb.y, xb.z, xb.w};
        float ec[8] = {e0.x, e0.y, e0.z, e0.w, e1.x, e1.y, e1.z, e1.w};
        #pragma unroll
        for (int r = 0; r < 8; r++)
            #pragma unroll
            for (int c = 0; c < 8; c++)
                acc[r][c] = fmaf(xr[r], ec[c], acc[r][c]);
    }

    if (jz <= NITEMS - 8) {
        #pragma unroll
        for (int r = 0; r < 8; r++) {
            float* sp = &g_scores[(size_t)(row0 + r0 + r) * NITEMS + jz];
            *reinterpret_cast<float4*>(sp) =
                make_float4(acc[r][0], acc[r][1], acc[r][2], acc[r][3]);
            *reinterpret_cast<float4*>(sp + 4) =
                make_float4(acc[r][4], acc[r][5], acc[r][6], acc[r][7]);
        }
    }
}

// ---------------- kernel 3: candidate top-256 by fp32, fp64 rescore, top-50 ----
__device__ __forceinline__ unsigned ordu(float f) {
    unsigned u = __float_as_uint(f);
    return (u & 0x80000000u) ? ~u : (u | 0x80000000u);
}
__device__ __forceinline__ unsigned long long ordu64(double d) {
    unsigned long long u = __double_as_longlong(d);
    return (u & 0x8000000000000000ull) ? ~u : (u | 0x8000000000000000ull);
}

__global__ __launch_bounds__(256) void k_topk(const float* __restrict__ E,
                                              float* __restrict__ out) {
    __shared__ union {
        unsigned hist[4096];
        unsigned long long keys[CAND_MAX];
    } u;
    __shared__ unsigned cidx[CAND_MAX];
    __shared__ float xrow[EMB];
    __shared__ unsigned strip[256];
    __shared__ int s_bin, s_cnt;
    __shared__ unsigned long long wkey[8];
    __shared__ unsigned wbi[8];
    __shared__ int wpos[8];

    const int row = blockIdx.x;
    const int tid = threadIdx.x;
    const int lane = tid & 31;
    const int warp = tid >> 5;
    const float4* s4 = reinterpret_cast<const float4*>(&g_scores[(size_t)row * NITEMS]);

    if (tid < EMB) xrow[tid] = g_xemb[row * EMB + tid];
    for (int b = tid; b < 4096; b += 256) u.hist[b] = 0;
    __syncthreads();

    // pass 1: 12-bit histogram of ordered-uint
    for (int i = tid; i < NITEMS / 4; i += 256) {
        float4 v = s4[i];
        atomicAdd(&u.hist[ordu(v.x) >> 20], 1u);
        atomicAdd(&u.hist[ordu(v.y) >> 20], 1u);
        atomicAdd(&u.hist[ordu(v.z) >> 20], 1u);
        atomicAdd(&u.hist[ordu(v.w) >> 20], 1u);
    }
    __syncthreads();

    // suffix scan for bin with above-count < CAND_TARGET <= inclusive-count
    unsigned loc = 0;
    #pragma unroll
    for (int q = 0; q < 16; q++) loc += u.hist[tid * 16 + q];
    strip[tid] = loc;
    __syncthreads();
    if (tid == 0) {
        int acc = 0, bin = 0;
        for (int t = 255; t >= 0; t--) {
            if (acc + (int)strip[t] >= CAND_TARGET) {
                for (int b = t * 16 + 15; b >= t * 16; b--) {
                    if (acc + (int)u.hist[b] >= CAND_TARGET) { bin = b; break; }
                    acc += (int)u.hist[b];
                }
                break;
            }
            acc += (int)strip[t];
        }
        s_bin = bin; s_cnt = 0;
    }
    __syncthreads();

    // pass 2: compact candidate indices (u >= bin lower edge)
    const unsigned thresh = ((unsigned)s_bin) << 20;
    for (int i = tid; i < NITEMS / 4; i += 256) {
        float4 v = s4[i];
        float vv[4] = {v.x, v.y, v.z, v.w};
        #pragma unroll
        for (int c = 0; c < 4; c++) {
            if (ordu(vv[c]) >= thresh) {
                int p = atomicAdd(&s_cnt, 1);
                if (p < CAND_MAX) cidx[p] = (unsigned)(4 * i + c);
            }
        }
    }
    __syncthreads();
    int cnt = s_cnt < CAND_MAX ? s_cnt : CAND_MAX;

    // fail-safe (unreachable on healthy data)
    if (cnt < TOPK) {
        for (int i = tid; i < CAND_MAX; i += 256) cidx[i] = (unsigned)i;
        cnt = CAND_MAX;
        __syncthreads();
    }

    // fp64 rescore: one warp per candidate; lane owns 4 dims (float4 of E row)
    __syncthreads();   // hist reads done; safe to alias u.keys
    for (int c = warp; c < cnt; c += 8) {
        const unsigned j = cidx[c];
        const float4* Ej4 = reinterpret_cast<const float4*>(&E[(size_t)j * EMB]);
        float4 ev = __ldg(&Ej4[lane]);
        float4 xv = *reinterpret_cast<const float4*>(&xrow[lane * 4]);
        double s = (double)xv.x * (double)ev.x + (double)xv.y * (double)ev.y
                 + (double)xv.z * (double)ev.z + (double)xv.w * (double)ev.w;
        #pragma unroll
        for (int off = 16; off; off >>= 1)
            s += __shfl_down_sync(0xffffffffu, s, off);
        if (lane == 0) u.keys[c] = ordu64(s);
    }
    __syncthreads();

    // 50 selections: fp64 value desc, item index asc on ties
    for (int k = 0; k < TOPK; k++) {
        unsigned long long bk = 0; unsigned bi = 0xffffffffu; int bp = -1;
        for (int i = tid; i < cnt; i += 256) {
            unsigned long long kk = u.keys[i];
            unsigned ii = cidx[i];
            if (kk > bk || (kk == bk && ii < bi)) { bk = kk; bi = ii; bp = i; }
        }
        #pragma unroll
        for (int off = 16; off; off >>= 1) {
            unsigned long long ok = __shfl_down_sync(0xffffffffu, bk, off);
            unsigned oi = __shfl_down_sync(0xffffffffu, bi, off);
            int op = __shfl_down_sync(0xffffffffu, bp, off);
            if (ok > bk || (ok == bk && oi < bi)) { bk = ok; bi = oi; bp = op; }
        }
        if (lane == 0) { wkey[warp] = bk; wbi[warp] = bi; wpos[warp] = bp; }
        __syncthreads();
        if (tid == 0) {
            unsigned long long fb = 0; unsigned fi = 0xffffffffu; int fp = -1;
            #pragma unroll
            for (int w = 0; w < 8; w++)
                if (wkey[w] > fb || (wkey[w] == fb && wbi[w] < fi)) {
                    fb = wkey[w]; fi = wbi[w]; fp = wpos[w];
                }
            out[row * TOPK + k] = (float)fi;
            if (fp >= 0) u.keys[fp] = 0;
        }
        __syncthreads();
    }
}

// ---------------- launch ----------------
extern "C" void kernel_launch(void* const* d_in, const int* in_sizes, int n_in,
                              void* d_out, int out_size) {
    const float* a0 = (const float*)d_in[0];
    const float* a1 = (const float*)d_in[1];
    const bool first_is_x = (in_sizes[0] == BATCH * NITEMS) ||
                            (in_sizes[0] == BATCH * NITEMS * 4);
    const float* x = first_is_x ? a0 : a1;             // [1024, 100000]
    const float* E = first_is_x ? a1 : a0;             // [100000, 128]
    float* out = (float*)d_out;                        // [1024, 50] float32 indices

    k_transposeE<<<dim3(NITEMS / 32, EMB / 32), dim3(32, 8)>>>(E);
    k_gemm1<<<dim3(BATCH / RB1, SPLIT), 256>>>(x, E);
    k_reduce<<<(BATCH * EMB + 255) / 256, 256>>>();
    k_gemm2<<<dim3((NITEMS + JT - 1) / JT, BATCH / RT), G2_THREADS>>>();
    k_topk<<<BATCH, 256>>>(E, out);
}

// round 10
// speedup vs baseline: 2.0869x; 1.1328x over previous
#include <cuda_runtime.h>
#include <cuda_bf16.h>
#include <cstdint>

// ---------------- problem constants ----------------
#define BATCH    1024
#define NITEMS   100000
#define EMB      128
#define TOPK     50

// gemm1 tiling: 128 rows x 128 dims per block, K-split over items
#define SPLIT    125         // K-split over NITEMS
#define KC       800         // NITEMS / SPLIT
#define TI       16          // item chunk staged in smem
#define RB       128         // rows per block
#define SPAD     132         // smem row pad (floats)

// gemm2 (tensor core) tiling
#define JTILE    128         // items per block
#define RTILE    128         // rows per block
#define KCH      32          // dim chunk staged in smem
#define APAD     36          // smem pad for fragment-friendly banks

#define CAND_TARGET 256
#define CAND_MAX    2048

// ---------------- device scratch (static: no allocations) ----------------
__device__ float g_part[(size_t)SPLIT * BATCH * EMB];   // 65.5 MB
__device__ float g_xemb[BATCH * EMB];                   // 0.5 MB
__device__ float g_scores[(size_t)BATCH * NITEMS];      // 409.6 MB

// ---------------- tf32 helpers ----------------
__device__ __forceinline__ uint32_t f2tf32(float f) {
    uint32_t u;
    asm("cvt.rna.tf32.f32 %0, %1;" : "=r"(u) : "f"(f));
    return u;
}
__device__ __forceinline__ void mma_tf32(float c[4],
                                         uint32_t a0, uint32_t a1, uint32_t a2, uint32_t a3,
                                         uint32_t b0, uint32_t b1) {
    asm("mma.sync.aligned.m16n8k8.row.col.f32.tf32.tf32.f32 "
        "{%0,%1,%2,%3}, {%4,%5,%6,%7}, {%8,%9}, {%0,%1,%2,%3};"
        : "+f"(c[0]), "+f"(c[1]), "+f"(c[2]), "+f"(c[3])
        : "r"(a0), "r"(a1), "r"(a2), "r"(a3), "r"(b0), "r"(b1));
}

// ---------------- kernel 1: x_emb partials = x @ E (fp32, K-split) -------------
// Block: 128 rows x 128 dims, 256 threads, thread tile 8x8.
// Two-level fp32 accumulation (facc per 16-item chunk -> gacc) keeps x_emb
// error ~1e-4 absolute: the exact-ranking zone given fp64 rescore downstream.
__global__ __launch_bounds__(256) void k_gemm1(const float* __restrict__ x,
                                               const float* __restrict__ E) {
    __shared__ float xs[TI][SPAD];   // [item][row]
    __shared__ float Es[TI][SPAD];   // [item][dim]
    const int tid  = threadIdx.x;
    const int rg   = tid >> 4;       // 0..15 row group
    const int dg   = tid & 15;       // 0..15 dim group
    const int row0 = blockIdx.x * RB;
    const int i0   = blockIdx.y * KC;
    const int r0   = rg * 8;
    const int d0   = dg * 8;

    float gacc[8][8];
    #pragma unroll
    for (int r = 0; r < 8; r++)
        #pragma unroll
        for (int c = 0; c < 8; c++) gacc[r][c] = 0.f;

    for (int ic = 0; ic < KC; ic += TI) {
        __syncthreads();
        // stage x chunk [128 rows][16 items] transposed -> xs[i][r]
        for (int t = tid; t < RB * (TI / 4); t += 256) {
            int r  = t >> 2;
            int iv = t & 3;
            float4 v = *reinterpret_cast<const float4*>(
                &x[(size_t)(row0 + r) * NITEMS + i0 + ic + iv * 4]);
            xs[iv * 4 + 0][r] = v.x;
            xs[iv * 4 + 1][r] = v.y;
            xs[iv * 4 + 2][r] = v.z;
            xs[iv * 4 + 3][r] = v.w;
        }
        // stage E chunk [16 items][128 dims] -> Es[i][d]
        for (int t = tid; t < TI * (EMB / 4); t += 256) {
            int i  = t >> 5;
            int dq = t & 31;
            float4 v = *reinterpret_cast<const float4*>(
                &E[(size_t)(i0 + ic + i) * EMB + dq * 4]);
            *reinterpret_cast<float4*>(&Es[i][dq * 4]) = v;
        }
        __syncthreads();

        float facc[8][8];
        #pragma unroll
        for (int r = 0; r < 8; r++)
            #pragma unroll
            for (int c = 0; c < 8; c++) facc[r][c] = 0.f;

        #pragma unroll
        for (int k = 0; k < TI; k++) {
            float4 xa = *reinterpret_cast<const float4*>(&xs[k][r0]);
            float4 xb = *reinterpret_cast<const float4*>(&xs[k][r0 + 4]);
            float4 ea = *reinterpret_cast<const float4*>(&Es[k][d0]);
            float4 eb = *reinterpret_cast<const float4*>(&Es[k][d0 + 4]);
            float xr[8] = {xa.x, xa.y, xa.z, xa.w, xb.x, xb.y, xb.z, xb.w};
            float ec[8] = {ea.x, ea.y, ea.z, ea.w, eb.x, eb.y, eb.z, eb.w};
            #pragma unroll
            for (int r = 0; r < 8; r++)
                #pragma unroll
                for (int c = 0; c < 8; c++)
                    facc[r][c] = fmaf(xr[r], ec[c], facc[r][c]);
        }
        #pragma unroll
        for (int r = 0; r < 8; r++)
            #pragma unroll
            for (int c = 0; c < 8; c++) gacc[r][c] += facc[r][c];
    }

    float* part = &g_part[(size_t)blockIdx.y * BATCH * EMB];
    #pragma unroll
    for (int r = 0; r < 8; r++) {
        float* pp = &part[(size_t)(row0 + r0 + r) * EMB + d0];
        *reinterpret_cast<float4*>(pp) =
            make_float4(gacc[r][0], gacc[r][1], gacc[r][2], gacc[r][3]);
        *reinterpret_cast<float4*>(pp + 4) =
            make_float4(gacc[r][4], gacc[r][5], gacc[r][6], gacc[r][7]);
    }
}

// ---------------- kernel 1b: fold K-split partials in fp64 ----------------
__global__ __launch_bounds__(256) void k_reduce() {
    int i = blockIdx.x * blockDim.x + threadIdx.x;
    if (i < BATCH * EMB) {
        double sum = 0.0;
        for (int s = 0; s < SPLIT; s++) sum += (double)g_part[(size_t)s * BATCH * EMB + i];
        g_xemb[i] = (float)sum;
    }
}

// ---------------- kernel 2: scores = x_emb @ E^T  (tf32 tensor cores) ----------
// Block: 128 rows x 128 items, 8 warps; warp w owns rows w*16..w*16+15.
// K=128 split into 4 staged chunks of 32 dims. E consumed row-major directly
// as the col-major B operand (B[k][n] = E[item n][dim k]) -- no transpose needed.
// tf32 precision is candidate-grade only; fp64 rescore in k_topk finalizes.
__global__ __launch_bounds__(256) void k_gemm2_tc(const float* __restrict__ E) {
    __shared__ uint32_t As[RTILE][APAD];   // x_emb tile  [row][dim]  (tf32 bits)
    __shared__ uint32_t Bs[JTILE][APAD];   // E tile      [item][dim] (tf32 bits)
    const int tid  = threadIdx.x;
    const int lane = tid & 31;
    const int warp = tid >> 5;
    const int row0 = blockIdx.y * RTILE;
    const int j0   = blockIdx.x * JTILE;
    const int g    = lane >> 2;            // 0..7
    const int c    = lane & 3;             // 0..3

    float cr[16][4];
    #pragma unroll
    for (int nt = 0; nt < 16; nt++)
        #pragma unroll
        for (int q = 0; q < 4; q++) cr[nt][q] = 0.f;

    for (int kc = 0; kc < EMB; kc += KCH) {
        __syncthreads();
        // stage A chunk: 128 rows x 32 dims of x_emb
        for (int t = tid; t < RTILE * (KCH / 4); t += 256) {
            int r  = t >> 3;
            int kq = t & 7;
            float4 v = *reinterpret_cast<const float4*>(
                &g_xemb[(size_t)(row0 + r) * EMB + kc + kq * 4]);
            uint4 u = make_uint4(f2tf32(v.x), f2tf32(v.y), f2tf32(v.z), f2tf32(v.w));
            *reinterpret_cast<uint4*>(&As[r][kq * 4]) = u;
        }
        // stage B chunk: 128 items x 32 dims of E (clamp tail items; stores guarded)
        for (int t = tid; t < JTILE * (KCH / 4); t += 256) {
            int r  = t >> 3;
            int kq = t & 7;
            int jj = j0 + r;
            if (jj >= NITEMS) jj = NITEMS - 1;
            float4 v = *reinterpret_cast<const float4*>(
                &E[(size_t)jj * EMB + kc + kq * 4]);
            uint4 u = make_uint4(f2tf32(v.x), f2tf32(v.y), f2tf32(v.z), f2tf32(v.w));
            *reinterpret_cast<uint4*>(&Bs[r][kq * 4]) = u;
        }
        __syncthreads();

        #pragma unroll
        for (int s = 0; s < KCH / 8; s++) {
            const int k0 = s * 8;
            uint32_t a0 = As[warp * 16 + g][k0 + c];
            uint32_t a1 = As[warp * 16 + 8 + g][k0 + c];
            uint32_t a2 = As[warp * 16 + g][k0 + c + 4];
            uint32_t a3 = As[warp * 16 + 8 + g][k0 + c + 4];
            #pragma unroll
            for (int nt = 0; nt < 16; nt++) {
                uint32_t b0 = Bs[nt * 8 + g][k0 + c];
                uint32_t b1 = Bs[nt * 8 + g][k0 + c + 4];
                mma_tf32(cr[nt], a0, a1, a2, a3, b0, b1);
            }
        }
    }

    // store C: rows warp*16+g (+8), cols j0 + nt*8 + 2c (+1).  NITEMS % 8 == 0.
    #pragma unroll
    for (int nt = 0; nt < 16; nt++) {
        if (j0 + nt * 8 + 8 <= NITEMS) {
            int jz = j0 + nt * 8 + 2 * c;
            int r  = row0 + warp * 16 + g;
            float2 v01 = make_float2(cr[nt][0], cr[nt][1]);
            float2 v23 = make_float2(cr[nt][2], cr[nt][3]);
            *reinterpret_cast<float2*>(&g_scores[(size_t)r * NITEMS + jz]) = v01;
            *reinterpret_cast<float2*>(&g_scores[(size_t)(r + 8) * NITEMS + jz]) = v23;
        }
    }
}

// ---------------- kernel 3: top-256 candidates by tf32 score, fp64 rescore ------
__device__ __forceinline__ unsigned ordu(float f) {
    unsigned u = __float_as_uint(f);
    return (u & 0x80000000u) ? ~u : (u | 0x80000000u);
}
__device__ __forceinline__ unsigned long long ordu64(double d) {
    unsigned long long u = __double_as_longlong(d);
    return (u & 0x8000000000000000ull) ? ~u : (u | 0x8000000000000000ull);
}

__global__ __launch_bounds__(256) void k_topk(const float* __restrict__ E,
                                              float* __restrict__ out) {
    __shared__ union {
        unsigned hist[4096];
        unsigned long long keys[CAND_MAX];
    } u;
    __shared__ unsigned cidx[CAND_MAX];
    __shared__ float xrow[EMB];
    __shared__ unsigned strip[256];
    __shared__ int s_bin, s_cnt;
    __shared__ unsigned long long wkey[8];
    __shared__ unsigned wbi[8];
    __shared__ int wpos[8];

    const int row = blockIdx.x;
    const int tid = threadIdx.x;
    const int lane = tid & 31;
    const int warp = tid >> 5;
    const float4* s4 = reinterpret_cast<const float4*>(&g_scores[(size_t)row * NITEMS]);

    if (tid < EMB) xrow[tid] = g_xemb[row * EMB + tid];
    for (int b = tid; b < 4096; b += 256) u.hist[b] = 0;
    __syncthreads();

    for (int i = tid; i < NITEMS / 4; i += 256) {
        float4 v = s4[i];
        atomicAdd(&u.hist[ordu(v.x) >> 20], 1u);
        atomicAdd(&u.hist[ordu(v.y) >> 20], 1u);
        atomicAdd(&u.hist[ordu(v.z) >> 20], 1u);
        atomicAdd(&u.hist[ordu(v.w) >> 20], 1u);
    }
    __syncthreads();

    unsigned loc = 0;
    #pragma unroll
    for (int q = 0; q < 16; q++) loc += u.hist[tid * 16 + q];
    strip[tid] = loc;
    __syncthreads();
    if (tid == 0) {
        int acc = 0, bin = 0;
        for (int t = 255; t >= 0; t--) {
            if (acc + (int)strip[t] >= CAND_TARGET) {
                for (int b = t * 16 + 15; b >= t * 16; b--) {
                    if (acc + (int)u.hist[b] >= CAND_TARGET) { bin = b; break; }
                    acc += (int)u.hist[b];
                }
                break;
            }
            acc += (int)strip[t];
        }
        s_bin = bin; s_cnt = 0;
    }
    __syncthreads();

    const unsigned thresh = ((unsigned)s_bin) << 20;
    for (int i = tid; i < NITEMS / 4; i += 256) {
        float4 v = s4[i];
        float vv[4] = {v.x, v.y, v.z, v.w};
        #pragma unroll
        for (int c = 0; c < 4; c++) {
            if (ordu(vv[c]) >= thresh) {
                int p = atomicAdd(&s_cnt, 1);
                if (p < CAND_MAX) cidx[p] = (unsigned)(4 * i + c);
            }
        }
    }
    __syncthreads();
    int cnt = s_cnt < CAND_MAX ? s_cnt : CAND_MAX;

    if (cnt < TOPK) {
        for (int i = tid; i < CAND_MAX; i += 256) cidx[i] = (unsigned)i;
        cnt = CAND_MAX;
        __syncthreads();
    }

    __syncthreads();   // hist reads done; safe to alias u.keys
    for (int c = warp; c < cnt; c += 8) {
        const unsigned j = cidx[c];
        const float4* Ej4 = reinterpret_cast<const float4*>(&E[(size_t)j * EMB]);
        float4 ev = __ldg(&Ej4[lane]);
        float4 xv = *reinterpret_cast<const float4*>(&xrow[lane * 4]);
        double s = (double)xv.x * (double)ev.x + (double)xv.y * (double)ev.y
                 + (double)xv.z * (double)ev.z + (double)xv.w * (double)ev.w;
        #pragma unroll
        for (int off = 16; off; off >>= 1)
            s += __shfl_down_sync(0xffffffffu, s, off);
        if (lane == 0) u.keys[c] = ordu64(s);
    }
    __syncthreads();

    for (int k = 0; k < TOPK; k++) {
        unsigned long long bk = 0; unsigned bi = 0xffffffffu; int bp = -1;
        for (int i = tid; i < cnt; i += 256) {
            unsigned long long kk = u.keys[i];
            unsigned ii = cidx[i];
            if (kk > bk || (kk == bk && ii < bi)) { bk = kk; bi = ii; bp = i; }
        }
        #pragma unroll
        for (int off = 16; off; off >>= 1) {
            unsigned long long ok = __shfl_down_sync(0xffffffffu, bk, off);
            unsigned oi = __shfl_down_sync(0xffffffffu, bi, off);
            int op = __shfl_down_sync(0xffffffffu, bp, off);
            if (ok > bk || (ok == bk && oi < bi)) { bk = ok; bi = oi; bp = op; }
        }
        if (lane == 0) { wkey[warp] = bk; wbi[warp] = bi; wpos[warp] = bp; }
        __syncthreads();
        if (tid == 0) {
            unsigned long long fb = 0; unsigned fi = 0xffffffffu; int fp = -1;
            #pragma unroll
            for (int w = 0; w < 8; w++)
                if (wkey[w] > fb || (wkey[w] == fb && wbi[w] < fi)) {
                    fb = wkey[w]; fi = wbi[w]; fp = wpos[w];
                }
            out[row * TOPK + k] = (float)fi;
            if (fp >= 0) u.keys[fp] = 0;
        }
        __syncthreads();
    }
}

// ---------------- launch ----------------
extern "C" void kernel_launch(void* const* d_in, const int* in_sizes, int n_in,
                              void* d_out, int out_size) {
    const float* a0 = (const float*)d_in[0];
    const float* a1 = (const float*)d_in[1];
    const bool first_is_x = (in_sizes[0] == BATCH * NITEMS) ||
                            (in_sizes[0] == BATCH * NITEMS * 4);
    const float* x = first_is_x ? a0 : a1;             // [1024, 100000]
    const float* E = first_is_x ? a1 : a0;             // [100000, 128]
    float* out = (float*)d_out;                        // [1024, 50] float32 indices

    k_gemm1<<<dim3(BATCH / RB, SPLIT), 256>>>(x, E);
    k_reduce<<<(BATCH * EMB + 255) / 256, 256>>>();
    k_gemm2_tc<<<dim3((NITEMS + JTILE - 1) / JTILE, BATCH / RTILE), 256>>>(E);
    k_topk<<<BATCH, 256>>>(E, out);
}

// round 13
// speedup vs baseline: 2.2053x; 1.0568x over previous
#include <cuda_runtime.h>
#include <cuda_bf16.h>
#include <cstdint>

// ---------------- problem constants ----------------
#define BATCH    1024
#define NITEMS   100000
#define EMB      128
#define TOPK     50

// gemm1 tiling: 128 rows x 128 dims per block, K-split over items
#define SPLIT    125         // K-split over NITEMS
#define KC       800         // NITEMS / SPLIT
#define TI       16          // item chunk staged in smem
#define RB       128         // rows per block
#define SPAD     132         // smem row pad (floats)

// gemm2 (tensor core) tiling
#define JTILE    128
#define RTILE    128
#define KCH      32
#define APAD     36

#define CAND_TARGET 256
#define CAND_MAX    2048

// ---------------- device scratch (static: no allocations) ----------------
__device__ float g_part[(size_t)SPLIT * BATCH * EMB];        // 65.5 MB
__device__ float g_xemb[BATCH * EMB];                        // 0.5 MB
__device__ __nv_bfloat16 g_scores[(size_t)BATCH * NITEMS];   // 204.8 MB

// ---------------- tf32 helpers ----------------
__device__ __forceinline__ uint32_t f2tf32(float f) {
    uint32_t u;
    asm("cvt.rna.tf32.f32 %0, %1;" : "=r"(u) : "f"(f));
    return u;
}
__device__ __forceinline__ void mma_tf32(float c[4],
                                         uint32_t a0, uint32_t a1, uint32_t a2, uint32_t a3,
                                         uint32_t b0, uint32_t b1) {
    asm("mma.sync.aligned.m16n8k8.row.col.f32.tf32.tf32.f32 "
        "{%0,%1,%2,%3}, {%4,%5,%6,%7}, {%8,%9}, {%0,%1,%2,%3};"
        : "+f"(c[0]), "+f"(c[1]), "+f"(c[2]), "+f"(c[3])
        : "r"(a0), "r"(a1), "r"(a2), "r"(a3), "r"(b0), "r"(b1));
}

// ---------------- kernel 1: x_emb partials = x @ E (fp32, K-split) -------------
// VERBATIM the round-10-passing version: per-thread FMA order (and hence x_emb
// bits) must stay identical to the configuration that matched the reference's
// ranking exactly. Do NOT change numerics here.
__global__ __launch_bounds__(256) void k_gemm1(const float* __restrict__ x,
                                               const float* __restrict__ E) {
    __shared__ float xs[TI][SPAD];   // [item][row]
    __shared__ float Es[TI][SPAD];   // [item][dim]
    const int tid  = threadIdx.x;
    const int rg   = tid >> 4;       // 0..15 row group
    const int dg   = tid & 15;       // 0..15 dim group
    const int row0 = blockIdx.x * RB;
    const int i0   = blockIdx.y * KC;
    const int r0   = rg * 8;
    const int d0   = dg * 8;

    float gacc[8][8];
    #pragma unroll
    for (int r = 0; r < 8; r++)
        #pragma unroll
        for (int c = 0; c < 8; c++) gacc[r][c] = 0.f;

    for (int ic = 0; ic < KC; ic += TI) {
        __syncthreads();
        // stage x chunk [128 rows][16 items] transposed -> xs[i][r]
        for (int t = tid; t < RB * (TI / 4); t += 256) {
            int r  = t >> 2;
            int iv = t & 3;
            float4 v = *reinterpret_cast<const float4*>(
                &x[(size_t)(row0 + r) * NITEMS + i0 + ic + iv * 4]);
            xs[iv * 4 + 0][r] = v.x;
            xs[iv * 4 + 1][r] = v.y;
            xs[iv * 4 + 2][r] = v.z;
            xs[iv * 4 + 3][r] = v.w;
        }
        // stage E chunk [16 items][128 dims] -> Es[i][d]
        for (int t = tid; t < TI * (EMB / 4); t += 256) {
            int i  = t >> 5;
            int dq = t & 31;
            float4 v = *reinterpret_cast<const float4*>(
                &E[(size_t)(i0 + ic + i) * EMB + dq * 4]);
            *reinterpret_cast<float4*>(&Es[i][dq * 4]) = v;
        }
        __syncthreads();

        float facc[8][8];
        #pragma unroll
        for (int r = 0; r < 8; r++)
            #pragma unroll
            for (int c = 0; c < 8; c++) facc[r][c] = 0.f;

        #pragma unroll
        for (int k = 0; k < TI; k++) {
            float4 xa = *reinterpret_cast<const float4*>(&xs[k][r0]);
            float4 xb = *reinterpret_cast<const float4*>(&xs[k][r0 + 4]);
            float4 ea = *reinterpret_cast<const float4*>(&Es[k][d0]);
            float4 eb = *reinterpret_cast<const float4*>(&Es[k][d0 + 4]);
            float xr[8] = {xa.x, xa.y, xa.z, xa.w, xb.x, xb.y, xb.z, xb.w};
            float ec[8] = {ea.x, ea.y, ea.z, ea.w, eb.x, eb.y, eb.z, eb.w};
            #pragma unroll
            for (int r = 0; r < 8; r++)
                #pragma unroll
                for (int c = 0; c < 8; c++)
                    facc[r][c] = fmaf(xr[r], ec[c], facc[r][c]);
        }
        #pragma unroll
        for (int r = 0; r < 8; r++)
            #pragma unroll
            for (int c = 0; c < 8; c++) gacc[r][c] += facc[r][c];
    }

    float* part = &g_part[(size_t)blockIdx.y * BATCH * EMB];
    #pragma unroll
    for (int r = 0; r < 8; r++) {
        float* pp = &part[(size_t)(row0 + r0 + r) * EMB + d0];
        *reinterpret_cast<float4*>(pp) =
            make_float4(gacc[r][0], gacc[r][1], gacc[r][2], gacc[r][3]);
        *reinterpret_cast<float4*>(pp + 4) =
            make_float4(gacc[r][4], gacc[r][5], gacc[r][6], gacc[r][7]);
    }
}

// ---------------- kernel 1b: fold K-split partials in fp64 ----------------
__global__ __launch_bounds__(256) void k_reduce() {
    int i = blockIdx.x * blockDim.x + threadIdx.x;
    if (i < BATCH * EMB) {
        double sum = 0.0;
        for (int s = 0; s < SPLIT; s++) sum += (double)g_part[(size_t)s * BATCH * EMB + i];
        g_xemb[i] = (float)sum;
    }
}

// ---------------- kernel 2: scores = x_emb @ E^T (tf32 TC, bf16 output) --------
__global__ __launch_bounds__(256) void k_gemm2_tc(const float* __restrict__ E) {
    __shared__ uint32_t As[RTILE][APAD];
    __shared__ uint32_t Bs[JTILE][APAD];
    const int tid  = threadIdx.x;
    const int lane = tid & 31;
    const int warp = tid >> 5;
    const int row0 = blockIdx.y * RTILE;
    const int j0   = blockIdx.x * JTILE;
    const int g    = lane >> 2;
    const int c    = lane & 3;

    float cr[16][4];
    #pragma unroll
    for (int nt = 0; nt < 16; nt++)
        #pragma unroll
        for (int q = 0; q < 4; q++) cr[nt][q] = 0.f;

    for (int kc = 0; kc < EMB; kc += KCH) {
        __syncthreads();
        for (int t = tid; t < RTILE * (KCH / 4); t += 256) {
            int r  = t >> 3;
            int kq = t & 7;
            float4 v = *reinterpret_cast<const float4*>(
                &g_xemb[(size_t)(row0 + r) * EMB + kc + kq * 4]);
            uint4 u = make_uint4(f2tf32(v.x), f2tf32(v.y), f2tf32(v.z), f2tf32(v.w));
            *reinterpret_cast<uint4*>(&As[r][kq * 4]) = u;
        }
        for (int t = tid; t < JTILE * (KCH / 4); t += 256) {
            int r  = t >> 3;
            int kq = t & 7;
            int jj = j0 + r;
            if (jj >= NITEMS) jj = NITEMS - 1;
            float4 v = *reinterpret_cast<const float4*>(
                &E[(size_t)jj * EMB + kc + kq * 4]);
            uint4 u = make_uint4(f2tf32(v.x), f2tf32(v.y), f2tf32(v.z), f2tf32(v.w));
            *reinterpret_cast<uint4*>(&Bs[r][kq * 4]) = u;
        }
        __syncthreads();

        #pragma unroll
        for (int s = 0; s < KCH / 8; s++) {
            const int k0 = s * 8;
            uint32_t a0 = As[warp * 16 + g][k0 + c];
            uint32_t a1 = As[warp * 16 + 8 + g][k0 + c];
            uint32_t a2 = As[warp * 16 + g][k0 + c + 4];
            uint32_t a3 = As[warp * 16 + 8 + g][k0 + c + 4];
            #pragma unroll
            for (int nt = 0; nt < 16; nt++) {
                uint32_t b0 = Bs[nt * 8 + g][k0 + c];
                uint32_t b1 = Bs[nt * 8 + g][k0 + c + 4];
                mma_tf32(cr[nt], a0, a1, a2, a3, b0, b1);
            }
        }
    }

    // bf16 epilogue: cols 2c,2c+1 adjacent -> one bfloat162 store per pair
    #pragma unroll
    for (int nt = 0; nt < 16; nt++) {
        if (j0 + nt * 8 + 8 <= NITEMS) {
            int jz = j0 + nt * 8 + 2 * c;
            int r  = row0 + warp * 16 + g;
            __nv_bfloat162 p01 = make_bfloat162(__float2bfloat16_rn(cr[nt][0]),
                                                __float2bfloat16_rn(cr[nt][1]));
            __nv_bfloat162 p23 = make_bfloat162(__float2bfloat16_rn(cr[nt][2]),
                                                __float2bfloat16_rn(cr[nt][3]));
            *reinterpret_cast<__nv_bfloat162*>(&g_scores[(size_t)r * NITEMS + jz]) = p01;
            *reinterpret_cast<__nv_bfloat162*>(&g_scores[(size_t)(r + 8) * NITEMS + jz]) = p23;
        }
    }
}

// ---------------- kernel 3: bf16 histogram top-256, fp64 rescore, top-50 -------
__device__ __forceinline__ unsigned ord16(unsigned h) {   // ordered bf16 (16-bit)
    return (h & 0x8000u) ? (0xffffu & ~h) : (h | 0x8000u);
}
__device__ __forceinline__ unsigned long long ordu64(double d) {
    unsigned long long u = __double_as_longlong(d);
    return (u & 0x8000000000000000ull) ? ~u : (u | 0x8000000000000000ull);
}

#define QHALF 6250          // half of the 12500 uint4 (8 bf16) per row

__global__ __launch_bounds__(256) void k_topk(const float* __restrict__ E,
                                              float* __restrict__ out) {
    __shared__ union {
        unsigned hist[4096];
        unsigned long long keys[CAND_MAX];
    } u;
    __shared__ unsigned cidx[CAND_MAX];
    __shared__ float xrow[EMB];
    __shared__ unsigned strip[256];
    __shared__ int s_bin, s_cnt;
    __shared__ unsigned long long wkey[8];
    __shared__ unsigned wbi[8];
    __shared__ int wpos[8];

    const int row = blockIdx.x;
    const int tid = threadIdx.x;
    const int lane = tid & 31;
    const int warp = tid >> 5;
    const uint4* s16 = reinterpret_cast<const uint4*>(&g_scores[(size_t)row * NITEMS]);

    if (tid < EMB) xrow[tid] = g_xemb[row * EMB + tid];
    for (int b = tid; b < 4096; b += 256) u.hist[b] = 0;
    __syncthreads();

    // pass 1: histogram of ordered-bf16 >> 4  (two batched loads per iter)
    for (int i = tid; i < QHALF; i += 256) {
        uint4 va = s16[i];
        uint4 vb = s16[i + QHALF];
        unsigned w[8] = {va.x, va.y, va.z, va.w, vb.x, vb.y, vb.z, vb.w};
        #pragma unroll
        for (int q = 0; q < 8; q++) {
            atomicAdd(&u.hist[ord16(w[q] & 0xffffu) >> 4], 1u);
            atomicAdd(&u.hist[ord16(w[q] >> 16) >> 4], 1u);
        }
    }
    __syncthreads();

    // suffix scan for bin with above-count < CAND_TARGET <= inclusive-count
    unsigned loc = 0;
    #pragma unroll
    for (int q = 0; q < 16; q++) loc += u.hist[tid * 16 + q];
    strip[tid] = loc;
    __syncthreads();
    if (tid == 0) {
        int acc = 0, bin = 0;
        for (int t = 255; t >= 0; t--) {
            if (acc + (int)strip[t] >= CAND_TARGET) {
                for (int b = t * 16 + 15; b >= t * 16; b--) {
                    if (acc + (int)u.hist[b] >= CAND_TARGET) { bin = b; break; }
                    acc += (int)u.hist[b];
                }
                break;
            }
            acc += (int)strip[t];
        }
        s_bin = bin; s_cnt = 0;
    }
    __syncthreads();

    // pass 2: compact candidate indices (ord16 >= bin lower edge)
    const unsigned thresh = ((unsigned)s_bin) << 4;
    for (int i = tid; i < QHALF; i += 256) {
        uint4 va = s16[i];
        uint4 vb = s16[i + QHALF];
        unsigned w[8] = {va.x, va.y, va.z, va.w, vb.x, vb.y, vb.z, vb.w};
        #pragma unroll
        for (int q = 0; q < 8; q++) {
            int base = (q < 4) ? (8 * i + 2 * q) : (8 * (i + QHALF) + 2 * (q - 4));
            if (ord16(w[q] & 0xffffu) >= thresh) {
                int p = atomicAdd(&s_cnt, 1);
                if (p < CAND_MAX) cidx[p] = (unsigned)base;
            }
            if (ord16(w[q] >> 16) >= thresh) {
                int p = atomicAdd(&s_cnt, 1);
                if (p < CAND_MAX) cidx[p] = (unsigned)(base + 1);
            }
        }
    }
    __syncthreads();
    int cnt = s_cnt < CAND_MAX ? s_cnt : CAND_MAX;

    if (cnt < TOPK) {   // fail-safe, unreachable on healthy data
        for (int i = tid; i < CAND_MAX; i += 256) cidx[i] = (unsigned)i;
        cnt = CAND_MAX;
        __syncthreads();
    }

    __syncthreads();   // hist reads done; safe to alias u.keys
    // fp64 rescore: one warp per candidate; lane owns 4 dims
    for (int c2 = warp; c2 < cnt; c2 += 8) {
        const unsigned j = cidx[c2];
        const float4* Ej4 = reinterpret_cast<const float4*>(&E[(size_t)j * EMB]);
        float4 ev = __ldg(&Ej4[lane]);
        float4 xv = *reinterpret_cast<const float4*>(&xrow[lane * 4]);
        double s = (double)xv.x * (double)ev.x + (double)xv.y * (double)ev.y
                 + (double)xv.z * (double)ev.z + (double)xv.w * (double)ev.w;
        #pragma unroll
        for (int off = 16; off; off >>= 1)
            s += __shfl_down_sync(0xffffffffu, s, off);
        if (lane == 0) u.keys[c2] = ordu64(s);
    }
    __syncthreads();

    // 50 selections: fp64 value desc, item index asc on ties
    for (int k = 0; k < TOPK; k++) {
        unsigned long long bk = 0; unsigned bi = 0xffffffffu; int bp = -1;
        for (int i = tid; i < cnt; i += 256) {
            unsigned long long kk = u.keys[i];
            unsigned ii = cidx[i];
            if (kk > bk || (kk == bk && ii < bi)) { bk = kk; bi = ii; bp = i; }
        }
        #pragma unroll
        for (int off = 16; off; off >>= 1) {
            unsigned long long ok = __shfl_down_sync(0xffffffffu, bk, off);
            unsigned oi = __shfl_down_sync(0xffffffffu, bi, off);
            int op = __shfl_down_sync(0xffffffffu, bp, off);
            if (ok > bk || (ok == bk && oi < bi)) { bk = ok; bi = oi; bp = op; }
        }
        if (lane == 0) { wkey[warp] = bk; wbi[warp] = bi; wpos[warp] = bp; }
        __syncthreads();
        if (tid == 0) {
            unsigned long long fb = 0; unsigned fi = 0xffffffffu; int fp = -1;
            #pragma unroll
            for (int w = 0; w < 8; w++)
                if (wkey[w] > fb || (wkey[w] == fb && wbi[w] < fi)) {
                    fb = wkey[w]; fi = wbi[w]; fp = wpos[w];
                }
            out[row * TOPK + k] = (float)fi;
            if (fp >= 0) u.keys[fp] = 0;
        }
        __syncthreads();
    }
}

// ---------------- launch ----------------
extern "C" void kernel_launch(void* const* d_in, const int* in_sizes, int n_in,
                              void* d_out, int out_size) {
    const float* a0 = (const float*)d_in[0];
    const float* a1 = (const float*)d_in[1];
    const bool first_is_x = (in_sizes[0] == BATCH * NITEMS) ||
                            (in_sizes[0] == BATCH * NITEMS * 4);
    const float* x = first_is_x ? a0 : a1;             // [1024, 100000]
    const float* E = first_is_x ? a1 : a0;             // [100000, 128]
    float* out = (float*)d_out;                        // [1024, 50] float32 indices

    k_gemm1<<<dim3(BATCH / RB, SPLIT), 256>>>(x, E);
    k_reduce<<<(BATCH * EMB + 255) / 256, 256>>>();
    k_gemm2_tc<<<dim3((NITEMS + JTILE - 1) / JTILE, BATCH / RTILE), 256>>>(E);
    k_topk<<<BATCH, 256>>>(E, out);
}